// round 1
// baseline (speedup 1.0000x reference)
#include <cuda_runtime.h>
#include <cuda_bf16.h>

// BoundaryLoss: loss = sum over (b,c,d,h,w) of Gx(q)^2 + 2*Gy(q)^2, normalized,
// where q = softmax(pred, axis=C) - onehot(target), sobel applied 2-D per depth
// slice (kernels have kd=1; padded depth edge slices contribute exactly 0).
//
// Shapes fixed by the dataset: pred (2,4,96,160,160) f32, target (2,96,160,160) i32.

#define BB 2
#define CC 4
#define DD 96
#define HH 160
#define WW 160

#define TW 32           // tile width  (w)
#define TH 32           // tile height (h); each thread computes 4 rows
#define HALO_W 34
#define HALO_H 34
#define PITCH 36        // padded smem row pitch

__device__ double g_sum;

__global__ void bl_zero_kernel() { g_sum = 0.0; }

__global__ __launch_bounds__(256)
void bl_main_kernel(const float* __restrict__ pred,
                    const int*   __restrict__ target)
{
    __shared__ float q[CC][HALO_H][PITCH];

    const int slice   = blockIdx.z;        // b*DD + d
    const int b       = slice / DD;
    const int d       = slice - b * DD;
    const int tile_w0 = blockIdx.x * TW;
    const int tile_h0 = blockIdx.y * TH;
    const int tid     = threadIdx.y * 32 + threadIdx.x;

    const int sliceHW     = HH * WW;            // 25600
    const int chanStride  = DD * HH * WW;       // 2457600
    const float* pred_bd  = pred   + (b * CC * DD + d) * sliceHW;
    const int*   tgt_bd   = target + (b * DD + d) * sliceHW;

    // ---- Phase 1: per-voxel q = softmax - onehot into smem (halo incl.) ----
    for (int p = tid; p < HALO_H * HALO_W; p += 256) {
        const int j = p / HALO_W;
        const int i = p - j * HALO_W;
        const int h = tile_h0 + j - 1;
        const int w = tile_w0 + i - 1;
        float q0 = 0.f, q1 = 0.f, q2 = 0.f, q3 = 0.f;
        if ((unsigned)h < (unsigned)HH && (unsigned)w < (unsigned)WW) {
            const int off = h * WW + w;
            const float x0 = pred_bd[off];
            const float x1 = pred_bd[off +     chanStride];
            const float x2 = pred_bd[off + 2 * chanStride];
            const float x3 = pred_bd[off + 3 * chanStride];
            const float m  = fmaxf(fmaxf(x0, x1), fmaxf(x2, x3));
            const float e0 = __expf(x0 - m);
            const float e1 = __expf(x1 - m);
            const float e2 = __expf(x2 - m);
            const float e3 = __expf(x3 - m);
            const float r  = __frcp_rn(e0 + e1 + e2 + e3);
            const int   t  = tgt_bd[off];
            q0 = e0 * r - (t == 0 ? 1.f : 0.f);
            q1 = e1 * r - (t == 1 ? 1.f : 0.f);
            q2 = e2 * r - (t == 2 ? 1.f : 0.f);
            q3 = e3 * r - (t == 3 ? 1.f : 0.f);
        }
        q[0][j][i] = q0;
        q[1][j][i] = q1;
        q[2][j][i] = q2;
        q[3][j][i] = q3;
    }
    __syncthreads();

    // ---- Phase 2: separable sobel, rolling window of row sums ----
    // Thread (tx, ty) computes column w = tile_w0 + tx, rows ty*4 .. ty*4+3.
    // Halo-local col: lw = tx+1; needed halo rows: jbase .. jbase+5.
    float acc = 0.f;
    const int lw    = threadIdx.x + 1;
    const int jbase = threadIdx.y * 4;

    #pragma unroll
    for (int c = 0; c < CC; c++) {
        float a, bq, cv;
        a = q[c][jbase][lw - 1]; bq = q[c][jbase][lw]; cv = q[c][jbase][lw + 1];
        float u0 = a + 2.f * bq + cv, v0 = cv - a;
        a = q[c][jbase + 1][lw - 1]; bq = q[c][jbase + 1][lw]; cv = q[c][jbase + 1][lw + 1];
        float u1 = a + 2.f * bq + cv, v1 = cv - a;
        #pragma unroll
        for (int r = 0; r < 4; r++) {
            const int j2 = jbase + 2 + r;
            a = q[c][j2][lw - 1]; bq = q[c][j2][lw]; cv = q[c][j2][lw + 1];
            const float u2 = a + 2.f * bq + cv;
            const float v2 = cv - a;
            const float gx = v0 + 2.f * v1 + v2;   // sign-flips irrelevant: squared
            const float gy = u2 - u0;
            acc += gx * gx + 2.f * gy * gy;
            u0 = u1; v0 = v1; u1 = u2; v1 = v2;
        }
    }

    // ---- Block reduction -> one double atomic per block ----
    #pragma unroll
    for (int o = 16; o > 0; o >>= 1)
        acc += __shfl_down_sync(0xffffffffu, acc, o);

    __shared__ float warpsum[8];
    if (threadIdx.x == 0) warpsum[threadIdx.y] = acc;
    __syncthreads();
    if (tid == 0) {
        float s = 0.f;
        #pragma unroll
        for (int i = 0; i < 8; i++) s += warpsum[i];
        atomicAdd(&g_sum, (double)s);
    }
}

__global__ void bl_finalize_kernel(float* __restrict__ out)
{
    // per_tensor = B*(D+2)*(H+2)*(W+2); then divide by num_classes C
    const double per_tensor = (double)BB * (DD + 2) * (HH + 2) * (WW + 2);
    out[0] = (float)(g_sum / per_tensor / (double)CC);
}

extern "C" void kernel_launch(void* const* d_in, const int* in_sizes, int n_in,
                              void* d_out, int out_size)
{
    const float* pred   = (const float*)d_in[0];
    const int*   target = (const int*)d_in[1];
    float*       out    = (float*)d_out;

    bl_zero_kernel<<<1, 1>>>();

    dim3 block(32, 8, 1);
    dim3 grid(WW / TW, HH / TH, BB * DD);   // 5 x 5 x 192 = 4800 blocks
    bl_main_kernel<<<grid, block>>>(pred, target);

    bl_finalize_kernel<<<1, 1>>>(out);
}

// round 2
// speedup vs baseline: 1.1076x; 1.1076x over previous
#include <cuda_runtime.h>
#include <cuda_bf16.h>

// BoundaryLoss: loss = sum_{b,c,d,h,w} Gx(q)^2 + 2*Gy(q)^2 (normalized),
// q = softmax(pred, axis=C) - onehot(target); sobel is 2-D per depth slice
// (kernels have kd=1; zero-padded depth edge output slices contribute 0;
// sz == sy^T of sx so the 3-channel sum collapses to Gx^2 + 2*Gy^2).
//
// Shapes fixed: pred (2,4,96,160,160) f32, target (2,96,160,160) i32.

#define BB 2
#define CC 4
#define DD 96
#define HH 160
#define WW 160

#define TH 16                       // output rows per block
#define HALO (TH + 2)               // 18 halo rows
#define RTILES (HH / TH)            // 10 row tiles per slice
#define NBLK (BB * DD * RTILES)     // 1920 blocks
#define NTHREADS 320                // (160, 2)

#define CHSTR (DD * HH * WW)        // pred channel stride in floats
#define CHSTR4 (CHSTR / 4)          // ... in float4

__device__ float g_partial[NBLK];
__device__ int   g_count = 0;       // reset by the last block each replay

__device__ __forceinline__ float softmax_q(float e, float inv, int t, int c) {
    return e * inv - (t == c ? 1.0f : 0.0f);
}

__global__ __launch_bounds__(NTHREADS)
void bl_main_kernel(const float* __restrict__ pred,
                    const int*   __restrict__ target,
                    float*       __restrict__ out)
{
    __shared__ float q[CC][HALO][WW];          // 46080 B
    __shared__ float warpsum[NTHREADS / 32];   // 10 warps
    __shared__ double dwarpsum[NTHREADS / 32];
    __shared__ bool  is_last;

    const int blk   = blockIdx.x;              // 0..NBLK-1
    const int rt    = blk % RTILES;
    const int slice = blk / RTILES;            // b*DD + d
    const int b     = slice / DD;
    const int d     = slice - b * DD;
    const int h0    = rt * TH;

    const float* pred_bd = pred + (size_t)(b * CC * DD + d) * (HH * WW);
    const int*   tgt_bd  = target + (size_t)(b * DD + d) * (HH * WW);

    const int tid = threadIdx.y * 160 + threadIdx.x;

    // ---- Phase 1: q = softmax - onehot, vectorized float4/int4, into smem ----
    for (int p = tid; p < HALO * (WW / 4); p += NTHREADS) {
        const int j  = p / (WW / 4);
        const int vc = p - j * (WW / 4);
        const int h  = h0 + j - 1;
        float4 q0, q1, q2, q3;
        if ((unsigned)h < (unsigned)HH) {
            const float4* pr = (const float4*)(pred_bd + h * WW) + vc;
            const float4 x0 = pr[0];
            const float4 x1 = pr[CHSTR4];
            const float4 x2 = pr[2 * CHSTR4];
            const float4 x3 = pr[3 * CHSTR4];
            const int4   t  = ((const int4*)(tgt_bd + h * WW))[vc];

            // lane .x
            {
                float m = fmaxf(fmaxf(x0.x, x1.x), fmaxf(x2.x, x3.x));
                float e0 = __expf(x0.x - m), e1 = __expf(x1.x - m);
                float e2 = __expf(x2.x - m), e3 = __expf(x3.x - m);
                float r = __frcp_rn(e0 + e1 + e2 + e3);
                q0.x = softmax_q(e0, r, t.x, 0); q1.x = softmax_q(e1, r, t.x, 1);
                q2.x = softmax_q(e2, r, t.x, 2); q3.x = softmax_q(e3, r, t.x, 3);
            }
            // lane .y
            {
                float m = fmaxf(fmaxf(x0.y, x1.y), fmaxf(x2.y, x3.y));
                float e0 = __expf(x0.y - m), e1 = __expf(x1.y - m);
                float e2 = __expf(x2.y - m), e3 = __expf(x3.y - m);
                float r = __frcp_rn(e0 + e1 + e2 + e3);
                q0.y = softmax_q(e0, r, t.y, 0); q1.y = softmax_q(e1, r, t.y, 1);
                q2.y = softmax_q(e2, r, t.y, 2); q3.y = softmax_q(e3, r, t.y, 3);
            }
            // lane .z
            {
                float m = fmaxf(fmaxf(x0.z, x1.z), fmaxf(x2.z, x3.z));
                float e0 = __expf(x0.z - m), e1 = __expf(x1.z - m);
                float e2 = __expf(x2.z - m), e3 = __expf(x3.z - m);
                float r = __frcp_rn(e0 + e1 + e2 + e3);
                q0.z = softmax_q(e0, r, t.z, 0); q1.z = softmax_q(e1, r, t.z, 1);
                q2.z = softmax_q(e2, r, t.z, 2); q3.z = softmax_q(e3, r, t.z, 3);
            }
            // lane .w
            {
                float m = fmaxf(fmaxf(x0.w, x1.w), fmaxf(x2.w, x3.w));
                float e0 = __expf(x0.w - m), e1 = __expf(x1.w - m);
                float e2 = __expf(x2.w - m), e3 = __expf(x3.w - m);
                float r = __frcp_rn(e0 + e1 + e2 + e3);
                q0.w = softmax_q(e0, r, t.w, 0); q1.w = softmax_q(e1, r, t.w, 1);
                q2.w = softmax_q(e2, r, t.w, 2); q3.w = softmax_q(e3, r, t.w, 3);
            }
        } else {
            q0 = q1 = q2 = q3 = make_float4(0.f, 0.f, 0.f, 0.f);
        }
        *(float4*)&q[0][j][4 * vc] = q0;
        *(float4*)&q[1][j][4 * vc] = q1;
        *(float4*)&q[2][j][4 * vc] = q2;
        *(float4*)&q[3][j][4 * vc] = q3;
    }
    __syncthreads();

    // ---- Phase 2: separable sobel with rolling row sums ----
    // Thread (tx, ty): column w = tx, output rows ty*8 .. ty*8+7 of the tile.
    const int w  = threadIdx.x;
    const int jb = threadIdx.y * 8;               // first halo row of the window
    const bool wl = (w > 0), wr = (w < WW - 1);

    float acc = 0.f;
    #pragma unroll
    for (int c = 0; c < CC; c++) {
        float a, bq, cv, u0, v0, u1, v1;
        a  = wl ? q[c][jb][w - 1] : 0.f;
        bq = q[c][jb][w];
        cv = wr ? q[c][jb][w + 1] : 0.f;
        u0 = a + 2.f * bq + cv;  v0 = cv - a;
        a  = wl ? q[c][jb + 1][w - 1] : 0.f;
        bq = q[c][jb + 1][w];
        cv = wr ? q[c][jb + 1][w + 1] : 0.f;
        u1 = a + 2.f * bq + cv;  v1 = cv - a;
        #pragma unroll
        for (int r = 0; r < 8; r++) {
            const int j2 = jb + 2 + r;
            a  = wl ? q[c][j2][w - 1] : 0.f;
            bq = q[c][j2][w];
            cv = wr ? q[c][j2][w + 1] : 0.f;
            const float u2 = a + 2.f * bq + cv;
            const float v2 = cv - a;
            const float gx = v0 + 2.f * v1 + v2;   // sign irrelevant: squared
            const float gy = u2 - u0;
            acc += gx * gx + 2.f * gy * gy;
            u0 = u1; v0 = v1; u1 = u2; v1 = v2;
        }
    }

    // ---- Block reduction -> per-block partial (plain store, no atomics) ----
    #pragma unroll
    for (int o = 16; o > 0; o >>= 1)
        acc += __shfl_down_sync(0xffffffffu, acc, o);
    if ((tid & 31) == 0) warpsum[tid >> 5] = acc;
    __syncthreads();

    if (tid == 0) {
        float s = 0.f;
        #pragma unroll
        for (int i = 0; i < NTHREADS / 32; i++) s += warpsum[i];
        g_partial[blk] = s;
        __threadfence();
        int cgot = atomicAdd(&g_count, 1);
        is_last = (cgot == NBLK - 1);
    }
    __syncthreads();

    // ---- Last block: final reduction, write out, reset counter ----
    if (is_last) {
        double s = 0.0;
        for (int i = tid; i < NBLK; i += NTHREADS) s += (double)g_partial[i];
        // reduce doubles across the block
        #pragma unroll
        for (int o = 16; o > 0; o >>= 1)
            s += __shfl_down_sync(0xffffffffu, s, o);
        if ((tid & 31) == 0) dwarpsum[tid >> 5] = s;
        __syncthreads();
        if (tid == 0) {
            double tot = 0.0;
            #pragma unroll
            for (int i = 0; i < NTHREADS / 32; i++) tot += dwarpsum[i];
            const double per_tensor = (double)BB * (DD + 2) * (HH + 2) * (WW + 2);
            out[0] = (float)(tot / per_tensor / (double)CC);
            g_count = 0;   // replay-safe reset
        }
    }
}

extern "C" void kernel_launch(void* const* d_in, const int* in_sizes, int n_in,
                              void* d_out, int out_size)
{
    const float* pred   = (const float*)d_in[0];
    const int*   target = (const int*)d_in[1];
    float*       out    = (float*)d_out;

    dim3 block(160, 2, 1);
    bl_main_kernel<<<NBLK, block>>>(pred, target, out);
}